// round 3
// baseline (speedup 1.0000x reference)
#include <cuda_runtime.h>

#define F        128
#define NRBF     20
#define TM       64
#define NTHREADS 256
#define SROW     132
// smem floats: s 64*132=8448 ; overlay 24576 ; w 24576 ; rn 192 ; idx 64
#define SMEM_FLOATS (8448 + 24576 + 24576 + 192 + 64)
#define SMEM_BYTES  (SMEM_FLOATS * 4)

__device__ float g_sum;

static __device__ __forceinline__ unsigned long long pack2(float x){
  unsigned long long u;
  asm("mov.b64 %0, {%1, %1};" : "=l"(u) : "f"(x));
  return u;
}
static __device__ __forceinline__ unsigned long long pack2f(float lo, float hi){
  unsigned long long u;
  asm("mov.b64 %0, {%1, %2};" : "=l"(u) : "f"(lo), "f"(hi));
  return u;
}
static __device__ __forceinline__ unsigned long long ffma2(unsigned long long a,
    unsigned long long b, unsigned long long c){
  unsigned long long d;
  asm("fma.rn.f32x2 %0, %1, %2, %3;" : "=l"(d) : "l"(a), "l"(b), "l"(c));
  return d;
}
static __device__ __forceinline__ void unpack2(unsigned long long u, float& lo, float& hi){
  asm("mov.b64 {%0, %1}, %2;" : "=f"(lo), "=f"(hi) : "l"(u));
}
static __device__ __forceinline__ void red4(float* p, float a, float b, float c, float d){
  asm volatile("red.global.add.v4.f32 [%0], {%1, %2, %3, %4};"
               :: "l"(p), "f"(a), "f"(b), "f"(c), "f"(d) : "memory");
}

__global__ void zero_gsum_kernel(){ g_sum = 0.f; }

__global__ void reduce_sumsq_kernel(const float* __restrict__ r, int n){
  float s = 0.f;
  for (int i = blockIdx.x * blockDim.x + threadIdx.x; i < n; i += gridDim.x * blockDim.x){
    float x = r[i];
    s = fmaf(x, x, s);
  }
  #pragma unroll
  for (int o = 16; o > 0; o >>= 1) s += __shfl_xor_sync(0xffffffffu, s, o);
  __shared__ float ws[8];
  int lane = threadIdx.x & 31, w = threadIdx.x >> 5;
  if (lane == 0) ws[w] = s;
  __syncthreads();
  if (threadIdx.x < 32){
    s = (threadIdx.x < 8) ? ws[threadIdx.x] : 0.f;
    #pragma unroll
    for (int o = 4; o > 0; o >>= 1) s += __shfl_xor_sync(0xffffffffu, s, o);
    if (threadIdx.x == 0) atomicAdd(&g_sum, s);
  }
}

__global__ void __launch_bounds__(NTHREADS, 1)
fused_message_kernel(
    const float* __restrict__ s_g, const float* __restrict__ r_g,
    const float* __restrict__ v_g, const int*   __restrict__ idx_g,
    const float* __restrict__ Wp_g, const float* __restrict__ bphi_g,
    const float* __restrict__ Ww_g, const float* __restrict__ bw_g,
    float* __restrict__ out_v, float* __restrict__ out_s, int E)
{
  extern __shared__ float sm[];
  float* s_sm  = sm;                   // [64][SROW]
  float* ov_sm = sm + TM*SROW;         // overlay: prologue rbf+Ww, mainloop W_phi half [64][384]
  float* w_sm  = ov_sm + 24576;        // [64][384]
  float* rn_sm = w_sm + 24576;         // [64][3]
  int*  idx_sm = (int*)(rn_sm + TM*3); // [64]

  const int tid = threadIdx.x;
  const int tx  = tid & 15;   // feature group: owns n = {tx*4..+3} and {64+tx*4..+3} per chunk
  const int ty  = tid >> 4;   // edge group:    owns edges ty*4..ty*4+3
  const int eb  = blockIdx.x * TM;

  float* rbfO = ov_sm;             // [64][NRBF]
  float* WwO  = ov_sm + TM*NRBF;   // [20][384]

  // ---------------- prologue: rbf / rn / idx / Ww / s tile ----------------
  if (tid < TM){
    int e = eb + tid;
    if (e < E){
      float rx = r_g[3*e+0], ry = r_g[3*e+1], rz = r_g[3*e+2];
      float rn = sqrtf(fmaf(rx,rx, fmaf(ry,ry, rz*rz)));
      float invg = rsqrtf(g_sum);                 // global Frobenius norm of r
      rn_sm[tid*3+0] = rx*invg;
      rn_sm[tid*3+1] = ry*invg;
      rn_sm[tid*3+2] = rz*invg;
      idx_sm[tid] = idx_g[e];
      float inv_rn = 1.f/rn;
      const float c0 = 0.62831853071795864769f;   // pi / R_CUT
      #pragma unroll
      for (int k = 0; k < NRBF; k++){
        float t = sinf((float)(k+1) * c0 * rn) * inv_rn;
        rbfO[tid*NRBF + k] = (t <= 5.0f) ? 0.5f*(cosf(c0*t) + 1.f) : 0.f;
      }
    } else {
      rn_sm[tid*3+0]=0.f; rn_sm[tid*3+1]=0.f; rn_sm[tid*3+2]=0.f;
      idx_sm[tid]=0;
      #pragma unroll
      for (int k = 0; k < NRBF; k++) rbfO[tid*NRBF+k] = 0.f;
    }
  }
  for (int i = tid; i < NRBF*3*F; i += NTHREADS) WwO[i] = Ww_g[i];
  {
    const int lane = tid & 31, wrp = tid >> 5;
    const float4* s4 = (const float4*)s_g;
    #pragma unroll
    for (int j = 0; j < 8; j++){
      int el = wrp*8 + j;
      int e  = eb + el;
      float4 val = make_float4(0.f,0.f,0.f,0.f);
      if (e < E) val = s4[(size_t)e*(F/4) + lane];
      *((float4*)(s_sm + el*SROW) + lane) = val;
    }
  }
  __syncthreads();

  // ---------------- w tile: w = rbf @ W_w + b_w  (packed f32x2) ----------------
  {
    #pragma unroll
    for (int c = 0; c < 3; c++){
      unsigned long long wacc[4][2][2];
      {
        const float4 b0 = *(const float4*)(bw_g + c*F + tx*4);
        const float4 b1 = *(const float4*)(bw_g + c*F + 64 + tx*4);
        unsigned long long i00 = pack2f(b0.x,b0.y), i01 = pack2f(b0.z,b0.w);
        unsigned long long i10 = pack2f(b1.x,b1.y), i11 = pack2f(b1.z,b1.w);
        #pragma unroll
        for (int i = 0; i < 4; i++){
          wacc[i][0][0]=i00; wacc[i][0][1]=i01; wacc[i][1][0]=i10; wacc[i][1][1]=i11;
        }
      }
      #pragma unroll
      for (int k = 0; k < NRBF; k++){
        unsigned long long rb[4];
        #pragma unroll
        for (int i = 0; i < 4; i++) rb[i] = pack2(rbfO[(ty*4+i)*NRBF + k]);
        const ulonglong2 g0 = *(const ulonglong2*)(WwO + k*3*F + c*F + tx*4);
        const ulonglong2 g1 = *(const ulonglong2*)(WwO + k*3*F + c*F + 64 + tx*4);
        #pragma unroll
        for (int i = 0; i < 4; i++){
          wacc[i][0][0] = ffma2(rb[i], g0.x, wacc[i][0][0]);
          wacc[i][0][1] = ffma2(rb[i], g0.y, wacc[i][0][1]);
          wacc[i][1][0] = ffma2(rb[i], g1.x, wacc[i][1][0]);
          wacc[i][1][1] = ffma2(rb[i], g1.y, wacc[i][1][1]);
        }
      }
      #pragma unroll
      for (int i = 0; i < 4; i++){
        ulonglong2 st0; st0.x = wacc[i][0][0]; st0.y = wacc[i][0][1];
        ulonglong2 st1; st1.x = wacc[i][1][0]; st1.y = wacc[i][1][1];
        *(ulonglong2*)(w_sm + (ty*4+i)*3*F + c*F + tx*4)      = st0;
        *(ulonglong2*)(w_sm + (ty*4+i)*3*F + c*F + 64 + tx*4) = st1;
      }
    }
  }
  __syncthreads();

  // ---------------- GEMM: phi = s @ W_phi (packed f32x2, W staged in 2 halves) ----------------
  unsigned long long acc[3][4][2][2];
  #pragma unroll
  for (int c = 0; c < 3; c++)
    #pragma unroll
    for (int i = 0; i < 4; i++)
      #pragma unroll
      for (int q = 0; q < 2; q++){ acc[c][i][q][0] = 0ULL; acc[c][i][q][1] = 0ULL; }

  #pragma unroll 1
  for (int h = 0; h < 2; h++){
    {
      const float4* W4  = (const float4*)(Wp_g + h*64*3*F);
      float4*       ov4 = (float4*)ov_sm;
      #pragma unroll
      for (int i = 0; i < 24; i++)       // 24*256*4 = 24576 floats
        ov4[i*NTHREADS + tid] = W4[i*NTHREADS + tid];
    }
    __syncthreads();
    #pragma unroll 2
    for (int kk = 0; kk < 64; kk++){
      const int k = h*64 + kk;
      unsigned long long A[4];
      #pragma unroll
      for (int i = 0; i < 4; i++) A[i] = pack2(s_sm[(ty*4+i)*SROW + k]);
      #pragma unroll
      for (int c = 0; c < 3; c++){
        const ulonglong2 g0 = *(const ulonglong2*)(ov_sm + kk*3*F + c*F + tx*4);
        const ulonglong2 g1 = *(const ulonglong2*)(ov_sm + kk*3*F + c*F + 64 + tx*4);
        #pragma unroll
        for (int i = 0; i < 4; i++){
          acc[c][i][0][0] = ffma2(A[i], g0.x, acc[c][i][0][0]);
          acc[c][i][0][1] = ffma2(A[i], g0.y, acc[c][i][0][1]);
          acc[c][i][1][0] = ffma2(A[i], g1.x, acc[c][i][1][0]);
          acc[c][i][1][1] = ffma2(A[i], g1.y, acc[c][i][1][1]);
        }
      }
    }
    __syncthreads();
  }

  // ---------------- epilogue: gate + vectorized reductions ----------------
  float4 bph[3][2];
  #pragma unroll
  for (int c = 0; c < 3; c++){
    bph[c][0] = *(const float4*)(bphi_g + c*F + tx*4);
    bph[c][1] = *(const float4*)(bphi_g + c*F + 64 + tx*4);
  }

  #pragma unroll
  for (int i = 0; i < 4; i++){
    const int el = ty*4 + i;
    const int e  = eb + el;
    if (e < E){
      const int node = idx_sm[el];
      const float rn0 = rn_sm[el*3+0], rn1 = rn_sm[el*3+1], rn2 = rn_sm[el*3+2];
      float sv[2][4], ssv[2][4], sr[2][4];
      #pragma unroll
      for (int c = 0; c < 3; c++){
        #pragma unroll
        for (int q = 0; q < 2; q++){
          const float4 wq = *(const float4*)(w_sm + el*3*F + c*F + q*64 + tx*4);
          float lo0, hi0, lo1, hi1;
          unpack2(acc[c][i][q][0], lo0, hi0);
          unpack2(acc[c][i][q][1], lo1, hi1);
          const float4 bq = bph[c][q];
          float o0 = wq.x * (lo0 + bq.x);
          float o1 = wq.y * (hi0 + bq.y);
          float o2 = wq.z * (lo1 + bq.z);
          float o3 = wq.w * (hi1 + bq.w);
          float* dst = (c==0) ? sv[q] : (c==1) ? ssv[q] : sr[q];
          dst[0]=o0; dst[1]=o1; dst[2]=o2; dst[3]=o3;
        }
      }
      // out_s += ss
      float* osp = out_s + (size_t)node*F + tx*4;
      red4(osp,      ssv[0][0], ssv[0][1], ssv[0][2], ssv[0][3]);
      red4(osp + 64, ssv[1][0], ssv[1][1], ssv[1][2], ssv[1][3]);
      // out_v += sv*v + sr*rn[d]
      const float* vp  = v_g  + (size_t)e*3*F    + tx*4;
      float*       ovp = out_v + (size_t)node*3*F + tx*4;
      #pragma unroll
      for (int d = 0; d < 3; d++){
        const float rnd = (d==0) ? rn0 : (d==1) ? rn1 : rn2;
        #pragma unroll
        for (int q = 0; q < 2; q++){
          const float4 vv = *(const float4*)(vp + d*F + q*64);
          float m0 = fmaf(sv[q][0], vv.x, sr[q][0]*rnd);
          float m1 = fmaf(sv[q][1], vv.y, sr[q][1]*rnd);
          float m2 = fmaf(sv[q][2], vv.z, sr[q][2]*rnd);
          float m3 = fmaf(sv[q][3], vv.w, sr[q][3]*rnd);
          red4(ovp + d*F + q*64, m0, m1, m2, m3);
        }
      }
    }
  }
}

extern "C" void kernel_launch(void* const* d_in, const int* in_sizes, int n_in,
                              void* d_out, int out_size){
  const float* s_g  = (const float*)d_in[0];
  const float* r_g  = (const float*)d_in[1];
  const float* v_g  = (const float*)d_in[2];
  const int*   idx  = (const int*)  d_in[3];
  const float* Wp   = (const float*)d_in[4];
  const float* bphi = (const float*)d_in[5];
  const float* Ww   = (const float*)d_in[6];
  const float* bw   = (const float*)d_in[7];
  const int E = in_sizes[1] / 3;            // r is (E,3)
  const int N = out_size / (4*F);           // out = out_v (N*3*F) ++ out_s (N*F)
  float* out_v = (float*)d_out;
  float* out_s = out_v + (size_t)N*3*F;

  cudaMemsetAsync(d_out, 0, (size_t)out_size * sizeof(float));
  zero_gsum_kernel<<<1,1>>>();
  reduce_sumsq_kernel<<<512, 256>>>(r_g, 3*E);
  cudaFuncSetAttribute(fused_message_kernel,
                       cudaFuncAttributeMaxDynamicSharedMemorySize, SMEM_BYTES);
  const int blocks = (E + TM - 1) / TM;
  fused_message_kernel<<<blocks, NTHREADS, SMEM_BYTES>>>(
      s_g, r_g, v_g, idx, Wp, bphi, Ww, bw, out_v, out_s, E);
}

// round 5
// speedup vs baseline: 1.6538x; 1.6538x over previous
#include <cuda_runtime.h>
#include <cstdint>

#define F        128
#define TM       128
#define NTHREADS 256
#define NRBF     20

// smem offsets in FLOATS
#define OFF_S    0            // s tile  [128][132]            16896
#define OFF_B    16896        // W_phi chunk [128n][132k]      16896
#define OFF_RBF  33792        // rbf [128][28]                  3584
#define OFF_WW   37376        // W_w [3][128n][28k]            10752
#define OFF_IDX  48128        // 128 ints
#define OFF_RN   48256        // 128 * 4 floats
#define SMEM_FLOATS 48768
#define SMEM_BYTES  (SMEM_FLOATS * 4)

__device__ float g_sum;

static __device__ __forceinline__ uint32_t to_tf32(float x){
  uint32_t t;
  asm("cvt.rna.tf32.f32 %0, %1;" : "=r"(t) : "f"(x));
  return t;
}
static __device__ __forceinline__ void mma8(float c[4], uint32_t a0, uint32_t a1,
    uint32_t a2, uint32_t a3, uint32_t b0, uint32_t b1){
  asm volatile("mma.sync.aligned.m16n8k8.row.col.f32.tf32.tf32.f32 "
    "{%0,%1,%2,%3}, {%4,%5,%6,%7}, {%8,%9}, {%0,%1,%2,%3};"
    : "+f"(c[0]), "+f"(c[1]), "+f"(c[2]), "+f"(c[3])
    : "r"(a0), "r"(a1), "r"(a2), "r"(a3), "r"(b0), "r"(b1));
}
static __device__ __forceinline__ void red4(float* p, float a, float b, float c, float d){
  asm volatile("red.global.add.v4.f32 [%0], {%1, %2, %3, %4};"
               :: "l"(p), "f"(a), "f"(b), "f"(c), "f"(d) : "memory");
}

__global__ void zero_gsum_kernel(){ g_sum = 0.f; }

__global__ void reduce_zero_kernel(const float* __restrict__ r, int n,
                                   float4* __restrict__ out4, int nout4){
  for (int i = blockIdx.x * blockDim.x + threadIdx.x; i < nout4; i += gridDim.x * blockDim.x)
    out4[i] = make_float4(0.f, 0.f, 0.f, 0.f);
  float s = 0.f;
  for (int i = blockIdx.x * blockDim.x + threadIdx.x; i < n; i += gridDim.x * blockDim.x){
    float x = r[i];
    s = fmaf(x, x, s);
  }
  #pragma unroll
  for (int o = 16; o > 0; o >>= 1) s += __shfl_xor_sync(0xffffffffu, s, o);
  __shared__ float ws[8];
  int lane = threadIdx.x & 31, w = threadIdx.x >> 5;
  if (lane == 0) ws[w] = s;
  __syncthreads();
  if (threadIdx.x < 32){
    s = (threadIdx.x < 8) ? ws[threadIdx.x] : 0.f;
    #pragma unroll
    for (int o = 4; o > 0; o >>= 1) s += __shfl_xor_sync(0xffffffffu, s, o);
    if (threadIdx.x == 0) atomicAdd(&g_sum, s);
  }
}

// MODE 0: store sv; MODE 1: scatter out_s; MODE 2: combine with sv -> out_v
template<int MODE>
static __device__ __forceinline__ void run_chunk(
    const uint32_t* __restrict__ su, const float* __restrict__ smf,
    int wid, int lane, int eb, int E, int c,
    const float* __restrict__ bphi_g, const float* __restrict__ bw_g,
    const float* __restrict__ v_g,
    float* __restrict__ out_s, float* __restrict__ out_v,
    float (*sv)[4])
{
  const int r0 = wid * 16 + (lane >> 2);
  const int kb = lane & 3;
  const int ng = lane >> 2;

  float acc[16][4];
  #pragma unroll
  for (int nt = 0; nt < 16; nt++){
    acc[nt][0]=0.f; acc[nt][1]=0.f; acc[nt][2]=0.f; acc[nt][3]=0.f;
  }

  // phi = s @ Wphi_chunk
  #pragma unroll 4
  for (int ks = 0; ks < 16; ks++){
    const int k = ks * 8 + kb;
    uint32_t a0 = su[OFF_S + r0*132 + k];
    uint32_t a1 = su[OFF_S + (r0+8)*132 + k];
    uint32_t a2 = su[OFF_S + r0*132 + k + 4];
    uint32_t a3 = su[OFF_S + (r0+8)*132 + k + 4];
    #pragma unroll
    for (int nt = 0; nt < 16; nt++){
      const int n = nt * 8 + ng;
      uint32_t b0 = su[OFF_B + n*132 + k];
      uint32_t b1 = su[OFF_B + n*132 + k + 4];
      mma8(acc[nt], a0, a1, a2, a3, b0, b1);
    }
  }

  // rbf fragments (K padded 20->24, rows 20-23 zeroed)
  uint32_t ra[3][4];
  #pragma unroll
  for (int ks = 0; ks < 3; ks++){
    const int k = ks * 8 + kb;
    ra[ks][0] = su[OFF_RBF + r0*28 + k];
    ra[ks][1] = su[OFF_RBF + (r0+8)*28 + k];
    ra[ks][2] = su[OFF_RBF + r0*28 + k + 4];
    ra[ks][3] = su[OFF_RBF + (r0+8)*28 + k + 4];
  }

  const bool even = (lane & 1) == 0;
  const int rowT  = r0 + (even ? 0 : 8);
  const int eT    = eb + rowT;
  const int node  = ((const int*)(smf + OFF_IDX))[rowT];
  const int cb0   = ((lane & 3) >> 1) * 4;
  float rnx = 0.f, rny = 0.f, rnz = 0.f;
  if (MODE == 2){
    rnx = smf[OFF_RN + rowT*4 + 0];
    rny = smf[OFF_RN + rowT*4 + 1];
    rnz = smf[OFF_RN + rowT*4 + 2];
  }

  #pragma unroll
  for (int nt = 0; nt < 16; nt++){
    const int n = nt * 8 + ng;
    // w = rbf @ Ww_chunk for this n-tile
    float w4[4] = {0.f, 0.f, 0.f, 0.f};
    #pragma unroll
    for (int ks = 0; ks < 3; ks++){
      const int k = ks * 8 + kb;
      uint32_t wb0 = su[OFF_WW + (c*128 + n)*28 + k];
      uint32_t wb1 = su[OFF_WW + (c*128 + n)*28 + k + 4];
      mma8(w4, ra[ks][0], ra[ks][1], ra[ks][2], ra[ks][3], wb0, wb1);
    }
    const int cc = nt * 8 + 2 * (lane & 3);
    const float2 bp = *(const float2*)(bphi_g + c*F + cc);
    const float2 bw = *(const float2*)(bw_g   + c*F + cc);
    float s0 = (w4[0] + bw.x) * (acc[nt][0] + bp.x);
    float s1 = (w4[1] + bw.y) * (acc[nt][1] + bp.y);
    float s2 = (w4[2] + bw.x) * (acc[nt][2] + bp.x);
    float s3 = (w4[3] + bw.y) * (acc[nt][3] + bp.y);

    if (MODE == 0){
      sv[nt][0] = s0; sv[nt][1] = s1; sv[nt][2] = s2; sv[nt][3] = s3;
    } else if (MODE == 1){
      float x0 = __shfl_xor_sync(0xffffffffu, s0, 1);
      float x1 = __shfl_xor_sync(0xffffffffu, s1, 1);
      float x2 = __shfl_xor_sync(0xffffffffu, s2, 1);
      float x3 = __shfl_xor_sync(0xffffffffu, s3, 1);
      float q0 = even ? s0 : x2, q1 = even ? s1 : x3;
      float q2 = even ? x0 : s2, q3 = even ? x1 : s3;
      if (eT < E)
        red4(out_s + (size_t)node*F + nt*8 + cb0, q0, q1, q2, q3);
    } else {
      float y0 = __shfl_xor_sync(0xffffffffu, sv[nt][0], 1);
      float y1 = __shfl_xor_sync(0xffffffffu, sv[nt][1], 1);
      float y2 = __shfl_xor_sync(0xffffffffu, sv[nt][2], 1);
      float y3 = __shfl_xor_sync(0xffffffffu, sv[nt][3], 1);
      float x0 = __shfl_xor_sync(0xffffffffu, s0, 1);
      float x1 = __shfl_xor_sync(0xffffffffu, s1, 1);
      float x2 = __shfl_xor_sync(0xffffffffu, s2, 1);
      float x3 = __shfl_xor_sync(0xffffffffu, s3, 1);
      float pv0 = even ? sv[nt][0] : y2, pv1 = even ? sv[nt][1] : y3;
      float pv2 = even ? y0 : sv[nt][2], pv3 = even ? y1 : sv[nt][3];
      float pr0 = even ? s0 : x2, pr1 = even ? s1 : x3;
      float pr2 = even ? x0 : s2, pr3 = even ? x1 : s3;
      if (eT < E){
        const float* vp = v_g   + (size_t)eT   * 3*F + nt*8 + cb0;
        float*       op = out_v + (size_t)node * 3*F + nt*8 + cb0;
        #pragma unroll
        for (int d = 0; d < 3; d++){
          const float rd = (d == 0) ? rnx : (d == 1) ? rny : rnz;
          const float4 vv = *(const float4*)(vp + d*F);
          red4(op + d*F,
               fmaf(pv0, vv.x, pr0*rd), fmaf(pv1, vv.y, pr1*rd),
               fmaf(pv2, vv.z, pr2*rd), fmaf(pv3, vv.w, pr3*rd));
        }
      }
    }
  }
}

static __device__ __forceinline__ void stage_B(uint32_t* __restrict__ su,
    const float* __restrict__ Wp_g, int c, int tid){
  #pragma unroll 8
  for (int it = 0; it < 64; it++){
    int i = it * NTHREADS + tid;       // 16384 elements
    int kk = i >> 7, n = i & 127;
    su[OFF_B + n*132 + kk] = to_tf32(Wp_g[kk*384 + c*128 + n]);
  }
}

__global__ void __launch_bounds__(NTHREADS)
fused_message_kernel(
    const float* __restrict__ s_g, const float* __restrict__ r_g,
    const float* __restrict__ v_g, const int*   __restrict__ idx_g,
    const float* __restrict__ Wp_g, const float* __restrict__ bphi_g,
    const float* __restrict__ Ww_g, const float* __restrict__ bw_g,
    float* __restrict__ out_v, float* __restrict__ out_s, int E)
{
  extern __shared__ float smf[];
  uint32_t* su = (uint32_t*)smf;
  const int tid  = threadIdx.x;
  const int wid  = tid >> 5;
  const int lane = tid & 31;
  const int eb   = blockIdx.x * TM;

  // ---- prologue ----
  // s tile -> tf32 [128][132]
  {
    const float4* s4 = (const float4*)s_g;
    #pragma unroll
    for (int it = 0; it < 16; it++){
      int i = it * NTHREADS + tid;      // 4096 float4
      int m = i >> 5, q = i & 31;
      float4 val = make_float4(0.f, 0.f, 0.f, 0.f);
      if (eb + m < E) val = s4[(size_t)(eb + m) * 32 + q];
      uint4 t;
      t.x = to_tf32(val.x); t.y = to_tf32(val.y);
      t.z = to_tf32(val.z); t.w = to_tf32(val.w);
      *(uint4*)(su + OFF_S + m*132 + 4*q) = t;
    }
  }
  // zero the k=20..23 pads of rbf and Ww
  if (tid < 128) *(float4*)(smf + OFF_RBF + tid*28 + 20) = make_float4(0.f,0.f,0.f,0.f);
  for (int i = tid; i < 384; i += NTHREADS)
    *(float4*)(smf + OFF_WW + i*28 + 20) = make_float4(0.f,0.f,0.f,0.f);
  // rbf / rn / idx
  if (tid < TM){
    int ee = eb + tid;
    float rx = 0.f, ry = 0.f, rz = 0.f;
    int node = 0;
    if (ee < E){
      rx = r_g[3*ee+0]; ry = r_g[3*ee+1]; rz = r_g[3*ee+2];
      node = idx_g[ee];
    }
    ((int*)(smf + OFF_IDX))[tid] = node;
    float rn = sqrtf(fmaf(rx,rx, fmaf(ry,ry, rz*rz)));
    float invg = rsqrtf(g_sum);
    smf[OFF_RN + tid*4+0] = rx*invg;
    smf[OFF_RN + tid*4+1] = ry*invg;
    smf[OFF_RN + tid*4+2] = rz*invg;
    smf[OFF_RN + tid*4+3] = 0.f;
    if (ee < E){
      float inv_rn = 1.f / rn;
      const float c0 = 0.62831853071795864769f;  // pi / R_CUT
      #pragma unroll
      for (int k = 0; k < NRBF; k++){
        float t  = sinf((float)(k+1) * c0 * rn) * inv_rn;
        float rb = (t <= 5.0f) ? 0.5f*(cosf(c0*t) + 1.f) : 0.f;
        su[OFF_RBF + tid*28 + k] = to_tf32(rb);
      }
    } else {
      #pragma unroll
      for (int k = 0; k < NRBF; k++) su[OFF_RBF + tid*28 + k] = 0u;
    }
  }
  // Ww -> [3][128n][28k]
  for (int i = tid; i < NRBF * 384; i += NTHREADS){
    int kk = i / 384, g = i % 384;
    int c = g >> 7, n = g & 127;
    su[OFF_WW + (c*128 + n)*28 + kk] = to_tf32(Ww_g[i]);
  }
  __syncthreads();

  float sv[16][4];

  // chunk c=1 -> out_s
  stage_B(su, Wp_g, 1, tid);
  __syncthreads();
  run_chunk<1>(su, smf, wid, lane, eb, E, 1, bphi_g, bw_g, v_g, out_s, out_v, sv);
  __syncthreads();
  // chunk c=0 -> sv (registers)
  stage_B(su, Wp_g, 0, tid);
  __syncthreads();
  run_chunk<0>(su, smf, wid, lane, eb, E, 0, bphi_g, bw_g, v_g, out_s, out_v, sv);
  __syncthreads();
  // chunk c=2 -> sr, combine with sv and v -> out_v
  stage_B(su, Wp_g, 2, tid);
  __syncthreads();
  run_chunk<2>(su, smf, wid, lane, eb, E, 2, bphi_g, bw_g, v_g, out_s, out_v, sv);
}

extern "C" void kernel_launch(void* const* d_in, const int* in_sizes, int n_in,
                              void* d_out, int out_size){
  const float* s_g  = (const float*)d_in[0];
  const float* r_g  = (const float*)d_in[1];
  const float* v_g  = (const float*)d_in[2];
  const int*   idx  = (const int*)  d_in[3];
  const float* Wp   = (const float*)d_in[4];
  const float* bphi = (const float*)d_in[5];
  const float* Ww   = (const float*)d_in[6];
  const float* bw   = (const float*)d_in[7];
  const int E = in_sizes[1] / 3;            // r is (E,3)
  const int N = out_size / (4*F);           // out = out_v (N*3*F) ++ out_s (N*F)
  float* out_v = (float*)d_out;
  float* out_s = out_v + (size_t)N*3*F;

  zero_gsum_kernel<<<1,1>>>();
  reduce_zero_kernel<<<512, 256>>>(r_g, 3*E, (float4*)d_out, out_size/4);
  cudaFuncSetAttribute(fused_message_kernel,
                       cudaFuncAttributeMaxDynamicSharedMemorySize, SMEM_BYTES);
  const int blocks = (E + TM - 1) / TM;
  fused_message_kernel<<<blocks, NTHREADS, SMEM_BYTES>>>(
      s_g, r_g, v_g, idx, Wp, bphi, Ww, bw, out_v, out_s, E);
}